// round 1
// baseline (speedup 1.0000x reference)
#include <cuda_runtime.h>

// Problem constants
#define SLEN   4096
#define BATCH  2
#define DMODEL 768
#define NHEADS 12
#define HDIM   64
#define MROWS  (BATCH * SLEN)   // 8192
#define NQKV   (3 * DMODEL)     // 2304

// Scratch (allocation-free rule: __device__ globals)
__device__ float g_qkv[(size_t)MROWS * NQKV];   // [8192, 2304]
__device__ float g_ctx[(size_t)MROWS * DMODEL]; // [8192, 768]

// ---------------------------------------------------------------------------
// Tiled fp32 SGEMM: C[M,N] = A[M,K] @ B[K,N], all row-major.
// 128x128 tile, BK=8, 256 threads, 8x8 per thread.
// Requires M%128==0, N%128==0, K%8==0 (true for all our shapes).
// ---------------------------------------------------------------------------
__global__ __launch_bounds__(256, 2)
void sgemm128(const float* __restrict__ A, const float* __restrict__ B,
              float* __restrict__ C, int M, int N, int K) {
    __shared__ float As[8][128];
    __shared__ float Bs[8][128];

    const int tid = threadIdx.x;
    const int tx  = tid & 15;
    const int ty  = tid >> 4;
    const int bm  = blockIdx.y * 128;
    const int bn  = blockIdx.x * 128;

    // load indices: A tile 128x8 (one float4/thread), B tile 8x128 (one float4/thread)
    const int ar = tid >> 1;
    const int ac = (tid & 1) << 2;
    const int br = tid >> 5;
    const int bc = (tid & 31) << 2;

    float acc[8][8];
#pragma unroll
    for (int i = 0; i < 8; i++)
#pragma unroll
        for (int j = 0; j < 8; j++) acc[i][j] = 0.f;

    for (int k0 = 0; k0 < K; k0 += 8) {
        float4 av = *reinterpret_cast<const float4*>(A + (size_t)(bm + ar) * K + k0 + ac);
        float4 bv = *reinterpret_cast<const float4*>(B + (size_t)(k0 + br) * N + bn + bc);
        As[ac + 0][ar] = av.x;
        As[ac + 1][ar] = av.y;
        As[ac + 2][ar] = av.z;
        As[ac + 3][ar] = av.w;
        *reinterpret_cast<float4*>(&Bs[br][bc]) = bv;
        __syncthreads();

#pragma unroll
        for (int kk = 0; kk < 8; kk++) {
            float a[8], b[8];
            *(float4*)&a[0] = *(const float4*)&As[kk][(ty << 2)];
            *(float4*)&a[4] = *(const float4*)&As[kk][(ty << 2) + 64];
            *(float4*)&b[0] = *(const float4*)&Bs[kk][(tx << 2)];
            *(float4*)&b[4] = *(const float4*)&Bs[kk][(tx << 2) + 64];
#pragma unroll
            for (int i = 0; i < 8; i++)
#pragma unroll
                for (int j = 0; j < 8; j++) acc[i][j] += a[i] * b[j];
        }
        __syncthreads();
    }

#pragma unroll
    for (int ii = 0; ii < 2; ii++) {
#pragma unroll
        for (int i = 0; i < 4; i++) {
            int r = bm + (ty << 2) + i + ii * 64;
#pragma unroll
            for (int jj = 0; jj < 2; jj++) {
                int c = bn + (tx << 2) + jj * 64;
                float4 v = make_float4(acc[ii * 4 + i][jj * 4 + 0],
                                       acc[ii * 4 + i][jj * 4 + 1],
                                       acc[ii * 4 + i][jj * 4 + 2],
                                       acc[ii * 4 + i][jj * 4 + 3]);
                *reinterpret_cast<float4*>(C + (size_t)r * N + c) = v;
            }
        }
    }
}

// ---------------------------------------------------------------------------
// Causal flash attention (fp32, online softmax).
// Block = (q_tile of 64, head, batch). 256 threads: tx in [0,16) ty in [0,16).
// Thread owns S rows ty*4..+3 x cols tx*2..+1, O rows ty*4..+3 x cols tx*4..+3.
// Key tiles of 32 rows; loop only over non-fully-masked tiles.
// ---------------------------------------------------------------------------
__global__ __launch_bounds__(256, 2)
void attn_kernel() {
    __shared__ float Qs[64][65];
    __shared__ float Xs[32][65];  // K tile, then V tile
    __shared__ float Ps[64][33];

    const int tid = threadIdx.x;
    const int tx  = tid & 15;
    const int ty  = tid >> 4;
    const int qt  = blockIdx.x;
    const int h   = blockIdx.y;
    const int b   = blockIdx.z;
    const int qbase = qt * 64;
    const size_t rowb = (size_t)b * SLEN;

    // Load Q tile (64x64)
#pragma unroll
    for (int it = 0; it < 4; it++) {
        int i = tid + it * 256;
        int r = i >> 4, c = (i & 15) << 2;
        float4 v = *reinterpret_cast<const float4*>(
            g_qkv + (rowb + qbase + r) * NQKV + h * HDIM + c);
        Qs[r][c] = v.x; Qs[r][c + 1] = v.y; Qs[r][c + 2] = v.z; Qs[r][c + 3] = v.w;
    }

    float o[4][4];
    float m[4], l[4];
#pragma unroll
    for (int i = 0; i < 4; i++) {
        m[i] = -1e30f;
        l[i] = 0.f;
#pragma unroll
        for (int j = 0; j < 4; j++) o[i][j] = 0.f;
    }

    const int nkt = (qbase + 64) >> 5;  // key tiles needed for causal coverage
    for (int kt = 0; kt < nkt; kt++) {
        const int kb = kt << 5;
        __syncthreads();  // previous iteration's Xs/Ps reads complete

        // Load K tile (32x64)
#pragma unroll
        for (int it = 0; it < 2; it++) {
            int i = tid + it * 256;
            int r = i >> 4, c = (i & 15) << 2;
            float4 v = *reinterpret_cast<const float4*>(
                g_qkv + (rowb + kb + r) * NQKV + DMODEL + h * HDIM + c);
            Xs[r][c] = v.x; Xs[r][c + 1] = v.y; Xs[r][c + 2] = v.z; Xs[r][c + 3] = v.w;
        }
        __syncthreads();

        // S = Q @ K^T (rows ty*4..+3, cols tx*2..+1), accumulate in registers
        float s0[4] = {0.f, 0.f, 0.f, 0.f};
        float s1[4] = {0.f, 0.f, 0.f, 0.f};
#pragma unroll 8
        for (int d = 0; d < HDIM; d++) {
            float k0 = Xs[(tx << 1)][d];
            float k1 = Xs[(tx << 1) + 1][d];
#pragma unroll
            for (int i = 0; i < 4; i++) {
                float q = Qs[(ty << 2) + i][d];
                s0[i] += q * k0;
                s1[i] += q * k1;
            }
        }

        // Scale + causal mask
#pragma unroll
        for (int i = 0; i < 4; i++) {
            int qi  = qbase + (ty << 2) + i;
            int k0i = kb + (tx << 1);
            s0[i] = (k0i     <= qi) ? s0[i] * 0.125f : -1e30f;
            s1[i] = (k0i + 1 <= qi) ? s1[i] * 0.125f : -1e30f;
        }

        // Online softmax (row reductions across 16 tx lanes via shfl)
#pragma unroll
        for (int i = 0; i < 4; i++) {
            float mt = fmaxf(s0[i], s1[i]);
#pragma unroll
            for (int off = 8; off; off >>= 1)
                mt = fmaxf(mt, __shfl_xor_sync(0xffffffffu, mt, off));
            float mn   = fmaxf(m[i], mt);
            float corr = __expf(m[i] - mn);
            m[i] = mn;
            float p0 = __expf(s0[i] - mn);
            float p1 = __expf(s1[i] - mn);
            float rs = p0 + p1;
#pragma unroll
            for (int off = 8; off; off >>= 1)
                rs += __shfl_xor_sync(0xffffffffu, rs, off);
            l[i] = l[i] * corr + rs;
#pragma unroll
            for (int j = 0; j < 4; j++) o[i][j] *= corr;
            Ps[(ty << 2) + i][(tx << 1)]     = p0;
            Ps[(ty << 2) + i][(tx << 1) + 1] = p1;
        }
        __syncthreads();  // S-phase reads of Xs(K) done; Ps published

        // Load V tile (32x64) into Xs
#pragma unroll
        for (int it = 0; it < 2; it++) {
            int i = tid + it * 256;
            int r = i >> 4, c = (i & 15) << 2;
            float4 v = *reinterpret_cast<const float4*>(
                g_qkv + (rowb + kb + r) * NQKV + 2 * DMODEL + h * HDIM + c);
            Xs[r][c] = v.x; Xs[r][c + 1] = v.y; Xs[r][c + 2] = v.z; Xs[r][c + 3] = v.w;
        }
        __syncthreads();

        // O += P @ V (O cols tx*4..+3)
#pragma unroll 4
        for (int k = 0; k < 32; k++) {
            float vv[4];
#pragma unroll
            for (int j = 0; j < 4; j++) vv[j] = Xs[k][(tx << 2) + j];
#pragma unroll
            for (int i = 0; i < 4; i++) {
                float p = Ps[(ty << 2) + i][k];
#pragma unroll
                for (int j = 0; j < 4; j++) o[i][j] += p * vv[j];
            }
        }
    }

    // Normalize and write ctx [8192, 768]
#pragma unroll
    for (int i = 0; i < 4; i++) {
        float inv = 1.f / l[i];
        float4 v = make_float4(o[i][0] * inv, o[i][1] * inv,
                               o[i][2] * inv, o[i][3] * inv);
        *reinterpret_cast<float4*>(
            g_ctx + (rowb + qbase + (ty << 2) + i) * DMODEL + h * HDIM + (tx << 2)) = v;
    }
}

// ---------------------------------------------------------------------------
extern "C" void kernel_launch(void* const* d_in, const int* in_sizes, int n_in,
                              void* d_out, int out_size) {
    const float* x     = (const float*)d_in[0];
    const float* w_qkv = (const float*)d_in[1];
    const float* w_out = (const float*)d_in[2];
    float* out = (float*)d_out;

    float* qkvbuf = nullptr;
    float* ctxbuf = nullptr;
    cudaGetSymbolAddress((void**)&qkvbuf, g_qkv);
    cudaGetSymbolAddress((void**)&ctxbuf, g_ctx);

    dim3 blk(256);
    // 1) QKV projection: [8192,768] @ [768,2304]
    sgemm128<<<dim3(NQKV / 128, MROWS / 128), blk>>>(x, w_qkv, qkvbuf,
                                                     MROWS, NQKV, DMODEL);
    // 2) Causal attention -> ctx [8192,768]
    attn_kernel<<<dim3(SLEN / 64, NHEADS, BATCH), blk>>>();
    // 3) Output projection: [8192,768] @ [768,768]
    sgemm128<<<dim3(DMODEL / 128, MROWS / 128), blk>>>(ctxbuf, w_out, out,
                                                       MROWS, DMODEL, DMODEL);
}

// round 2
// speedup vs baseline: 5.9722x; 5.9722x over previous
#include <cuda_runtime.h>
#include <cuda_fp16.h>

#define SLEN   4096
#define BATCH  2
#define DMODEL 768
#define NHEADS 12
#define HDIM   64
#define MROWS  (BATCH * SLEN)   // 8192
#define NQKV   (3 * DMODEL)     // 2304

// ---------------- scratch (__device__ globals; no allocs allowed) ----------
__device__ __half g_xh[(size_t)MROWS * DMODEL];
__device__ __half g_xl[(size_t)MROWS * DMODEL];
__device__ __half g_wqkvh[(size_t)DMODEL * NQKV];
__device__ __half g_wqkvl[(size_t)DMODEL * NQKV];
__device__ __half g_wouth[(size_t)DMODEL * DMODEL];
__device__ __half g_woutl[(size_t)DMODEL * DMODEL];
__device__ __half g_qkvh[(size_t)MROWS * NQKV];              // fp16 Q|K|V
__device__ __half g_vT[(size_t)BATCH * NHEADS * HDIM * SLEN]; // V transposed [b,h,d,s]
__device__ __half g_ctxh[(size_t)MROWS * DMODEL];
__device__ __half g_ctxl[(size_t)MROWS * DMODEL];

// ---------------- helpers --------------------------------------------------
__device__ __forceinline__ void mma_f16(float c[4], const unsigned a[4], const unsigned b[2]) {
    asm volatile(
        "mma.sync.aligned.m16n8k16.row.col.f32.f16.f16.f32 "
        "{%0,%1,%2,%3}, {%4,%5,%6,%7}, {%8,%9}, {%0,%1,%2,%3};\n"
        : "+f"(c[0]), "+f"(c[1]), "+f"(c[2]), "+f"(c[3])
        : "r"(a[0]), "r"(a[1]), "r"(a[2]), "r"(a[3]), "r"(b[0]), "r"(b[1]));
}

__device__ __forceinline__ unsigned pack2(float x, float y) {
    __half2 h = __floats2half2_rn(x, y);
    return *reinterpret_cast<unsigned*>(&h);
}

// ---------------- fp32 -> (hi, lo) fp16 split ------------------------------
__global__ void split_kernel(const float* __restrict__ src,
                             __half* __restrict__ hi, __half* __restrict__ lo, int n4) {
    int i = blockIdx.x * blockDim.x + threadIdx.x;
    int stride = gridDim.x * blockDim.x;
    for (; i < n4; i += stride) {
        float4 v = reinterpret_cast<const float4*>(src)[i];
        __half h0 = __float2half_rn(v.x), h1 = __float2half_rn(v.y);
        __half h2 = __float2half_rn(v.z), h3 = __float2half_rn(v.w);
        __half l0 = __float2half_rn(v.x - __half2float(h0));
        __half l1 = __float2half_rn(v.y - __half2float(h1));
        __half l2 = __float2half_rn(v.z - __half2float(h2));
        __half l3 = __float2half_rn(v.w - __half2float(h3));
        reinterpret_cast<__half2*>(hi)[2 * i]     = __halves2half2(h0, h1);
        reinterpret_cast<__half2*>(hi)[2 * i + 1] = __halves2half2(h2, h3);
        reinterpret_cast<__half2*>(lo)[2 * i]     = __halves2half2(l0, l1);
        reinterpret_cast<__half2*>(lo)[2 * i + 1] = __halves2half2(l2, l3);
    }
}

// ---------------- 3x split-fp16 GEMM: C = A @ B ----------------------------
// A[M,K], B[K,N] row-major (fp16 hi/lo pairs). 128x128 block tile, BK=32,
// 256 threads = 8 warps (2x4), warp tile 64x32.
#define ASTR 40
#define BSTR 34
template <bool WRITE_HALF>
__global__ __launch_bounds__(256)
void hgemm3x(const __half* __restrict__ Ah, const __half* __restrict__ Al,
             const __half* __restrict__ Bh, const __half* __restrict__ Bl,
             float* __restrict__ Cf, __half* __restrict__ Ch,
             int M, int N, int K) {
    __shared__ __half As[2][128][ASTR];
    __shared__ __half Bs[2][128][BSTR];   // [n][k]

    const int tid  = threadIdx.x;
    const int lane = tid & 31;
    const int w    = tid >> 5;
    const int gid  = lane >> 2;
    const int tig  = lane & 3;
    const int wm   = (w >> 2) * 64;
    const int wn   = (w & 3) * 32;
    const int bm   = blockIdx.y * 128;
    const int bn   = blockIdx.x * 128;

    float acc[4][4][4];
#pragma unroll
    for (int i = 0; i < 4; i++)
#pragma unroll
        for (int j = 0; j < 4; j++)
#pragma unroll
            for (int e = 0; e < 4; e++) acc[i][j][e] = 0.f;

    for (int k0 = 0; k0 < K; k0 += 32) {
        // A tile: 128x32, uint2 (4 halves) per chunk
#pragma unroll
        for (int t = 0; t < 4; t++) {
            int c = tid + t * 256;
            int row = c >> 3, kc = (c & 7) << 2;
            *(uint2*)&As[0][row][kc] =
                *(const uint2*)(Ah + (size_t)(bm + row) * K + k0 + kc);
            *(uint2*)&As[1][row][kc] =
                *(const uint2*)(Al + (size_t)(bm + row) * K + k0 + kc);
        }
        // B tile: 32x128, transposed into Bs[n][k]
#pragma unroll
        for (int t = 0; t < 4; t++) {
            int c = tid + t * 256;
            int kr = c >> 5, nc = (c & 31) << 2;
            const __half* ph = Bh + (size_t)(k0 + kr) * N + bn + nc;
            const __half* pl = Bl + (size_t)(k0 + kr) * N + bn + nc;
            __half2 v0 = *(const __half2*)ph, v1 = *(const __half2*)(ph + 2);
            __half2 u0 = *(const __half2*)pl, u1 = *(const __half2*)(pl + 2);
            Bs[0][nc + 0][kr] = __low2half(v0);  Bs[0][nc + 1][kr] = __high2half(v0);
            Bs[0][nc + 2][kr] = __low2half(v1);  Bs[0][nc + 3][kr] = __high2half(v1);
            Bs[1][nc + 0][kr] = __low2half(u0);  Bs[1][nc + 1][kr] = __high2half(u0);
            Bs[1][nc + 2][kr] = __low2half(u1);  Bs[1][nc + 3][kr] = __high2half(u1);
        }
        __syncthreads();

#pragma unroll
        for (int kk = 0; kk < 32; kk += 16) {
            unsigned bf[2][4][2];
#pragma unroll
            for (int p = 0; p < 2; p++)
#pragma unroll
                for (int j = 0; j < 4; j++) {
                    int n = wn + j * 8 + gid;
                    bf[p][j][0] = *(const unsigned*)&Bs[p][n][kk + 2 * tig];
                    bf[p][j][1] = *(const unsigned*)&Bs[p][n][kk + 2 * tig + 8];
                }
#pragma unroll
            for (int i = 0; i < 4; i++) {
                int r = wm + i * 16 + gid;
                unsigned ah[4], al[4];
                ah[0] = *(const unsigned*)&As[0][r][kk + 2 * tig];
                ah[1] = *(const unsigned*)&As[0][r + 8][kk + 2 * tig];
                ah[2] = *(const unsigned*)&As[0][r][kk + 2 * tig + 8];
                ah[3] = *(const unsigned*)&As[0][r + 8][kk + 2 * tig + 8];
                al[0] = *(const unsigned*)&As[1][r][kk + 2 * tig];
                al[1] = *(const unsigned*)&As[1][r + 8][kk + 2 * tig];
                al[2] = *(const unsigned*)&As[1][r][kk + 2 * tig + 8];
                al[3] = *(const unsigned*)&As[1][r + 8][kk + 2 * tig + 8];
#pragma unroll
                for (int j = 0; j < 4; j++) {
                    mma_f16(acc[i][j], ah, bf[0][j]);  // Ah*Bh
                    mma_f16(acc[i][j], ah, bf[1][j]);  // Ah*Bl
                    mma_f16(acc[i][j], al, bf[0][j]);  // Al*Bh
                }
            }
        }
        __syncthreads();
    }

    // epilogue
#pragma unroll
    for (int i = 0; i < 4; i++)
#pragma unroll
        for (int j = 0; j < 4; j++) {
            int r0 = bm + wm + i * 16 + gid;
            int cc = bn + wn + j * 8 + 2 * tig;
            if (WRITE_HALF) {
                *(__half2*)(Ch + (size_t)r0 * N + cc) =
                    __floats2half2_rn(acc[i][j][0], acc[i][j][1]);
                *(__half2*)(Ch + (size_t)(r0 + 8) * N + cc) =
                    __floats2half2_rn(acc[i][j][2], acc[i][j][3]);
            } else {
                *(float2*)(Cf + (size_t)r0 * N + cc) =
                    make_float2(acc[i][j][0], acc[i][j][1]);
                *(float2*)(Cf + (size_t)(r0 + 8) * N + cc) =
                    make_float2(acc[i][j][2], acc[i][j][3]);
            }
        }
}

// ---------------- V transpose: g_qkvh V section -> [b,h,d,s] ---------------
__global__ void transpose_v() {
    __shared__ __half t[32][33];
    const int bh = blockIdx.z;              // b*12 + h
    const int s0 = blockIdx.x * 32;
    const int d0 = blockIdx.y * 32;
    const int b = bh / NHEADS, h = bh % NHEADS;
    const int tx = threadIdx.x & 31, ty = threadIdx.x >> 5;

#pragma unroll
    for (int k = 0; k < 4; k++) {
        int s = s0 + ty + k * 8;
        t[ty + k * 8][tx] =
            g_qkvh[((size_t)b * SLEN + s) * NQKV + 2 * DMODEL + h * HDIM + d0 + tx];
    }
    __syncthreads();
#pragma unroll
    for (int k = 0; k < 4; k++) {
        int d = d0 + ty + k * 8;
        g_vT[((size_t)bh * HDIM + d) * SLEN + s0 + tx] = t[tx][ty + k * 8];
    }
}

// ---------------- fp16 flash attention (mma) -------------------------------
// Block = (q_tile 64, head, batch), 128 threads = 4 warps; warp owns 16 q rows.
#define QSTR 72
__global__ __launch_bounds__(128)
void attn_mma() {
    __shared__ __half Qs[64][QSTR];
    __shared__ __half Ks[64][QSTR];
    __shared__ __half Vs[64][QSTR];   // [d][key]

    const int tid  = threadIdx.x;
    const int lane = tid & 31;
    const int w    = tid >> 5;
    const int gid  = lane >> 2;
    const int tig  = lane & 3;
    const int qt = blockIdx.x, h = blockIdx.y, b = blockIdx.z;
    const int qbase = qt * 64;
    const size_t rowb = (size_t)b * SLEN;
    const int bh = b * NHEADS + h;
    const __half2 qscale = __floats2half2_rn(0.125f, 0.125f);  // exact (2^-3)

    // Load Q (scaled by 1/8)
#pragma unroll
    for (int t = 0; t < 8; t++) {
        int c = tid + t * 128;
        int r = c >> 4, dc = (c & 15) << 2;
        uint2 v = *(const uint2*)(g_qkvh + (rowb + qbase + r) * NQKV + h * HDIM + dc);
        __half2 v0 = __hmul2(*reinterpret_cast<__half2*>(&v.x), qscale);
        __half2 v1 = __hmul2(*reinterpret_cast<__half2*>(&v.y), qscale);
        *(__half2*)&Qs[r][dc]     = v0;
        *(__half2*)&Qs[r][dc + 2] = v1;
    }

    float m[2] = {-1e30f, -1e30f}, l[2] = {0.f, 0.f};
    float o[8][4];
#pragma unroll
    for (int j = 0; j < 8; j++)
#pragma unroll
        for (int e = 0; e < 4; e++) o[j][e] = 0.f;

    const int nkt = qt + 1;
    for (int kt = 0; kt < nkt; kt++) {
        const int kb = kt * 64;
        __syncthreads();
        // K tile
#pragma unroll
        for (int t = 0; t < 8; t++) {
            int c = tid + t * 128;
            int r = c >> 4, dc = (c & 15) << 2;
            *(uint2*)&Ks[r][dc] = *(const uint2*)(
                g_qkvh + (rowb + kb + r) * NQKV + DMODEL + h * HDIM + dc);
        }
        // V tile (pre-transposed): Vs[d][key]
#pragma unroll
        for (int t = 0; t < 8; t++) {
            int c = tid + t * 128;
            int d = c >> 4, sc = (c & 15) << 2;
            *(uint2*)&Vs[d][sc] = *(const uint2*)(
                g_vT + ((size_t)bh * HDIM + d) * SLEN + kb + sc);
        }
        __syncthreads();

        // S = (Q/8) @ K^T
        float s[8][4];
#pragma unroll
        for (int j = 0; j < 8; j++)
#pragma unroll
            for (int e = 0; e < 4; e++) s[j][e] = 0.f;
#pragma unroll
        for (int kc = 0; kc < 64; kc += 16) {
            unsigned a[4];
            int r = w * 16 + gid;
            a[0] = *(const unsigned*)&Qs[r][kc + 2 * tig];
            a[1] = *(const unsigned*)&Qs[r + 8][kc + 2 * tig];
            a[2] = *(const unsigned*)&Qs[r][kc + 2 * tig + 8];
            a[3] = *(const unsigned*)&Qs[r + 8][kc + 2 * tig + 8];
#pragma unroll
            for (int j = 0; j < 8; j++) {
                unsigned bb[2];
                int n = j * 8 + gid;
                bb[0] = *(const unsigned*)&Ks[n][kc + 2 * tig];
                bb[1] = *(const unsigned*)&Ks[n][kc + 2 * tig + 8];
                mma_f16(s[j], a, bb);
            }
        }

        // causal mask (diagonal tile only)
        const int row0 = qbase + w * 16 + gid;
        const int row1 = row0 + 8;
        if (kt == qt) {
#pragma unroll
            for (int j = 0; j < 8; j++) {
                int c0 = kb + 8 * j + 2 * tig;
                if (c0 > row0)     s[j][0] = -1e30f;
                if (c0 + 1 > row0) s[j][1] = -1e30f;
                if (c0 > row1)     s[j][2] = -1e30f;
                if (c0 + 1 > row1) s[j][3] = -1e30f;
            }
        }

        // online softmax (rows r0, r1 per thread; reduce over tig lanes)
        float mt0 = -1e30f, mt1 = -1e30f;
#pragma unroll
        for (int j = 0; j < 8; j++) {
            mt0 = fmaxf(mt0, fmaxf(s[j][0], s[j][1]));
            mt1 = fmaxf(mt1, fmaxf(s[j][2], s[j][3]));
        }
#pragma unroll
        for (int off = 1; off <= 2; off <<= 1) {
            mt0 = fmaxf(mt0, __shfl_xor_sync(0xffffffffu, mt0, off));
            mt1 = fmaxf(mt1, __shfl_xor_sync(0xffffffffu, mt1, off));
        }
        float mn0 = fmaxf(m[0], mt0), mn1 = fmaxf(m[1], mt1);
        float corr0 = __expf(m[0] - mn0), corr1 = __expf(m[1] - mn1);
        m[0] = mn0; m[1] = mn1;
        float rs0 = 0.f, rs1 = 0.f;
#pragma unroll
        for (int j = 0; j < 8; j++) {
            s[j][0] = __expf(s[j][0] - mn0);
            s[j][1] = __expf(s[j][1] - mn0);
            s[j][2] = __expf(s[j][2] - mn1);
            s[j][3] = __expf(s[j][3] - mn1);
            rs0 += s[j][0] + s[j][1];
            rs1 += s[j][2] + s[j][3];
        }
#pragma unroll
        for (int off = 1; off <= 2; off <<= 1) {
            rs0 += __shfl_xor_sync(0xffffffffu, rs0, off);
            rs1 += __shfl_xor_sync(0xffffffffu, rs1, off);
        }
        l[0] = l[0] * corr0 + rs0;
        l[1] = l[1] * corr1 + rs1;
#pragma unroll
        for (int j = 0; j < 8; j++) {
            o[j][0] *= corr0; o[j][1] *= corr0;
            o[j][2] *= corr1; o[j][3] *= corr1;
        }

        // P fragments (C-layout == A-layout trick), then O += P @ V
        unsigned pa[4][4];
#pragma unroll
        for (int kc = 0; kc < 4; kc++) {
            pa[kc][0] = pack2(s[2 * kc][0], s[2 * kc][1]);
            pa[kc][1] = pack2(s[2 * kc][2], s[2 * kc][3]);
            pa[kc][2] = pack2(s[2 * kc + 1][0], s[2 * kc + 1][1]);
            pa[kc][3] = pack2(s[2 * kc + 1][2], s[2 * kc + 1][3]);
        }
#pragma unroll
        for (int kc = 0; kc < 4; kc++)
#pragma unroll
            for (int j = 0; j < 8; j++) {
                unsigned bb[2];
                int n = j * 8 + gid;
                bb[0] = *(const unsigned*)&Vs[n][16 * kc + 2 * tig];
                bb[1] = *(const unsigned*)&Vs[n][16 * kc + 2 * tig + 8];
                mma_f16(o[j], pa[kc], bb);
            }
    }

    // normalize, split to hi/lo fp16, store ctx
    const float inv0 = 1.f / l[0], inv1 = 1.f / l[1];
    const size_t r0g = rowb + qbase + w * 16 + gid;
#pragma unroll
    for (int j = 0; j < 8; j++) {
        int col = h * HDIM + 8 * j + 2 * tig;
        float v0 = o[j][0] * inv0, v1 = o[j][1] * inv0;
        float v2 = o[j][2] * inv1, v3 = o[j][3] * inv1;
        __half h0 = __float2half_rn(v0), h1 = __float2half_rn(v1);
        __half h2 = __float2half_rn(v2), h3 = __float2half_rn(v3);
        *(__half2*)(g_ctxh + r0g * DMODEL + col) = __halves2half2(h0, h1);
        *(__half2*)(g_ctxh + (r0g + 8) * DMODEL + col) = __halves2half2(h2, h3);
        *(__half2*)(g_ctxl + r0g * DMODEL + col) =
            __halves2half2(__float2half_rn(v0 - __half2float(h0)),
                           __float2half_rn(v1 - __half2float(h1)));
        *(__half2*)(g_ctxl + (r0g + 8) * DMODEL + col) =
            __halves2half2(__float2half_rn(v2 - __half2float(h2)),
                           __float2half_rn(v3 - __half2float(h3)));
    }
}

// ---------------------------------------------------------------------------
extern "C" void kernel_launch(void* const* d_in, const int* in_sizes, int n_in,
                              void* d_out, int out_size) {
    const float* x     = (const float*)d_in[0];
    const float* w_qkv = (const float*)d_in[1];
    const float* w_out = (const float*)d_in[2];
    float* out = (float*)d_out;

    __half *xh, *xl, *wqh, *wql, *woh, *wol;
    cudaGetSymbolAddress((void**)&xh,  g_xh);
    cudaGetSymbolAddress((void**)&xl,  g_xl);
    cudaGetSymbolAddress((void**)&wqh, g_wqkvh);
    cudaGetSymbolAddress((void**)&wql, g_wqkvl);
    cudaGetSymbolAddress((void**)&woh, g_wouth);
    cudaGetSymbolAddress((void**)&wol, g_woutl);
    __half *qkvh, *ctxh, *ctxl;
    cudaGetSymbolAddress((void**)&qkvh, g_qkvh);
    cudaGetSymbolAddress((void**)&ctxh, g_ctxh);
    cudaGetSymbolAddress((void**)&ctxl, g_ctxl);

    split_kernel<<<256, 256>>>(x, xh, xl, MROWS * DMODEL / 4);
    split_kernel<<<256, 256>>>(w_qkv, wqh, wql, DMODEL * NQKV / 4);
    split_kernel<<<256, 256>>>(w_out, woh, wol, DMODEL * DMODEL / 4);

    // QKV projection (fp16 out)
    hgemm3x<true><<<dim3(NQKV / 128, MROWS / 128), 256>>>(
        xh, xl, wqh, wql, nullptr, qkvh, MROWS, NQKV, DMODEL);

    // V transpose for PV mma
    transpose_v<<<dim3(SLEN / 32, HDIM / 32, BATCH * NHEADS), 256>>>();

    // causal attention -> ctx (hi/lo fp16)
    attn_mma<<<dim3(SLEN / 64, NHEADS, BATCH), 128>>>();

    // output projection (fp32 out)
    hgemm3x<false><<<dim3(DMODEL / 128, MROWS / 128), 256>>>(
        ctxh, ctxl, woh, wol, out, nullptr, MROWS, DMODEL, DMODEL);
}

// round 4
// speedup vs baseline: 11.1560x; 1.8680x over previous
#include <cuda_runtime.h>
#include <cuda_fp16.h>
#include <cstdint>
#include <cstddef>

#define SLEN   4096
#define BATCH  2
#define DMODEL 768
#define NHEADS 12
#define HDIM   64
#define MROWS  (BATCH * SLEN)   // 8192
#define NQKV   (3 * DMODEL)     // 2304

// ---------------- scratch (__device__ globals) -----------------------------
__device__ __half g_xh[(size_t)MROWS * DMODEL];
__device__ __half g_wqkvh[(size_t)DMODEL * NQKV];   // transposed [N][K]
__device__ __half g_wqkvl[(size_t)DMODEL * NQKV];   // transposed [N][K]
__device__ __half g_wouth[(size_t)DMODEL * DMODEL]; // transposed [N][K]
__device__ __half g_woutl[(size_t)DMODEL * DMODEL]; // transposed [N][K]
__device__ __half g_qkvh[(size_t)MROWS * NQKV];     // fp16 Q|K|V
__device__ __half g_vT[(size_t)BATCH * NHEADS * HDIM * SLEN]; // V^T [b,h,d,s]
__device__ __half g_ctxh[(size_t)MROWS * DMODEL];

// ---------------- helpers --------------------------------------------------
__device__ __forceinline__ uint32_t s2u(const void* p) {
    return (uint32_t)__cvta_generic_to_shared(p);
}
__device__ __forceinline__ uint32_t swz(uint32_t b) {           // SW128
    return b ^ ((b >> 3) & 0x70);
}
__device__ __forceinline__ void ldsm4(uint32_t r[4], uint32_t addr) {
    asm volatile("ldmatrix.sync.aligned.m8n8.x4.shared.b16 {%0,%1,%2,%3}, [%4];"
                 : "=r"(r[0]), "=r"(r[1]), "=r"(r[2]), "=r"(r[3]) : "r"(addr));
}
__device__ __forceinline__ void cp16(uint32_t dst, const void* src) {
    asm volatile("cp.async.cg.shared.global [%0], [%1], 16;" :: "r"(dst), "l"(src));
}
__device__ __forceinline__ void mma_f16(float c[4], const uint32_t a[4],
                                        const uint32_t b[2]) {
    asm volatile(
        "mma.sync.aligned.m16n8k16.row.col.f32.f16.f16.f32 "
        "{%0,%1,%2,%3}, {%4,%5,%6,%7}, {%8,%9}, {%0,%1,%2,%3};\n"
        : "+f"(c[0]), "+f"(c[1]), "+f"(c[2]), "+f"(c[3])
        : "r"(a[0]), "r"(a[1]), "r"(a[2]), "r"(a[3]), "r"(b[0]), "r"(b[1]));
}
__device__ __forceinline__ unsigned pack2(float x, float y) {
    __half2 h = __floats2half2_rn(x, y);
    return *reinterpret_cast<unsigned*>(&h);
}

// ---------------- converts -------------------------------------------------
__global__ void to_half(const float* __restrict__ src, __half* __restrict__ dst, int n4) {
    int i = blockIdx.x * blockDim.x + threadIdx.x;
    int stride = gridDim.x * blockDim.x;
    for (; i < n4; i += stride) {
        float4 v = reinterpret_cast<const float4*>(src)[i];
        reinterpret_cast<__half2*>(dst)[2 * i]     = __floats2half2_rn(v.x, v.y);
        reinterpret_cast<__half2*>(dst)[2 * i + 1] = __floats2half2_rn(v.z, v.w);
    }
}

// W[K][N] fp32 -> WhT[N][K], WlT[N][K] fp16 hi/lo (transpose + split)
__global__ void split_wT(const float* __restrict__ W, __half* __restrict__ WhT,
                         __half* __restrict__ WlT, int K, int N) {
    __shared__ float t[32][33];
    const int k0 = blockIdx.y * 32, n0 = blockIdx.x * 32;
    const int tx = threadIdx.x & 31, ty = threadIdx.x >> 5;
#pragma unroll
    for (int m = 0; m < 4; m++)
        t[ty + 8 * m][tx] = W[(size_t)(k0 + ty + 8 * m) * N + n0 + tx];
    __syncthreads();
#pragma unroll
    for (int m = 0; m < 4; m++) {
        float v = t[tx][ty + 8 * m];
        __half h = __float2half_rn(v);
        size_t o = (size_t)(n0 + ty + 8 * m) * K + k0 + tx;
        WhT[o] = h;
        WlT[o] = __float2half_rn(v - __half2float(h));
    }
}

// ---------------- 2-pass split GEMM: C = A @ (Bh+Bl)^T ---------------------
// A[M][K] fp16, BhT/BlT [N][K] fp16. 128x128 tile, BK=64, 256 thr, 8 warps.
// cp.async double buffer + SW128 swizzle + ldmatrix.
#define TILEH 8192  // halves per 128x64 tile
template <bool WRITE_HALF>
__global__ __launch_bounds__(256)
void hgemm2x(const __half* __restrict__ A, const __half* __restrict__ Bht,
             const __half* __restrict__ Blt, float* __restrict__ Cf,
             __half* __restrict__ Ch, int M, int N, int K) {
    extern __shared__ __half sm[];
    const int tid = threadIdx.x, lane = tid & 31, w = tid >> 5;
    const int gid = lane >> 2, tig = lane & 3;
    const int wm = (w >> 2) * 64, wn = (w & 3) * 32;
    const int bm = blockIdx.y * 128, bn = blockIdx.x * 128;
    const uint32_t sb = s2u(sm);

    float acc[4][4][4];
#pragma unroll
    for (int i = 0; i < 4; i++)
#pragma unroll
        for (int j = 0; j < 4; j++)
#pragma unroll
            for (int e = 0; e < 4; e++) acc[i][j][e] = 0.f;

    const int nit = K >> 6;

#define LOAD_TILES(k0, buf)                                                        \
    {                                                                              \
        uint32_t base = sb + (uint32_t)(buf) * (3 * TILEH * 2);                    \
        _Pragma("unroll")                                                          \
        for (int p = 0; p < 4; p++) {                                              \
            int id = tid + p * 256;                                                \
            int row = id >> 3, chB = (id & 7) << 4;                                \
            uint32_t soff = swz((uint32_t)(row * 128 + chB));                      \
            cp16(base + soff,                                                      \
                 (const char*)(A + (size_t)(bm + row) * K + (k0)) + chB);          \
            cp16(base + TILEH * 2 + soff,                                          \
                 (const char*)(Bht + (size_t)(bn + row) * K + (k0)) + chB);        \
            cp16(base + 2 * TILEH * 2 + soff,                                      \
                 (const char*)(Blt + (size_t)(bn + row) * K + (k0)) + chB);        \
        }                                                                          \
        asm volatile("cp.async.commit_group;");                                    \
    }

    LOAD_TILES(0, 0);

    const int arow  = lane & 15;
    const int acolB = ((lane >> 4) << 3) * 2;
    const int brow  = ((lane >> 4) << 3) + (lane & 7);
    const int bcolB = (((lane >> 3) & 1) << 3) * 2;

    for (int it = 0; it < nit; it++) {
        asm volatile("cp.async.wait_group 0;");
        __syncthreads();
        if (it + 1 < nit) LOAD_TILES((it + 1) << 6, (it + 1) & 1);

        uint32_t aB  = sb + (uint32_t)(it & 1) * (3 * TILEH * 2);
        uint32_t bhB = aB + TILEH * 2;
        uint32_t blB = bhB + TILEH * 2;
#pragma unroll
        for (int kk = 0; kk < 64; kk += 16) {
            uint32_t af[4][4];
#pragma unroll
            for (int i = 0; i < 4; i++)
                ldsm4(af[i], aB + swz((uint32_t)((wm + 16 * i + arow) * 128 +
                                                 kk * 2 + acolB)));
#pragma unroll
            for (int jp = 0; jp < 2; jp++) {
                uint32_t bh[4], bl[4];
                uint32_t roff = (uint32_t)((wn + 16 * jp + brow) * 128 +
                                           kk * 2 + bcolB);
                ldsm4(bh, bhB + swz(roff));
                ldsm4(bl, blB + swz(roff));
#pragma unroll
                for (int i = 0; i < 4; i++) {
                    mma_f16(acc[i][2 * jp],     af[i], &bh[0]);
                    mma_f16(acc[i][2 * jp],     af[i], &bl[0]);
                    mma_f16(acc[i][2 * jp + 1], af[i], &bh[2]);
                    mma_f16(acc[i][2 * jp + 1], af[i], &bl[2]);
                }
            }
        }
        __syncthreads();
    }

    // epilogue
#pragma unroll
    for (int i = 0; i < 4; i++)
#pragma unroll
        for (int j = 0; j < 4; j++) {
            int r0 = bm + wm + i * 16 + gid;
            int cc = bn + wn + j * 8 + 2 * tig;
            if (WRITE_HALF) {
                *(__half2*)(Ch + (size_t)r0 * N + cc) =
                    __floats2half2_rn(acc[i][j][0], acc[i][j][1]);
                *(__half2*)(Ch + (size_t)(r0 + 8) * N + cc) =
                    __floats2half2_rn(acc[i][j][2], acc[i][j][3]);
            } else {
                *(float2*)(Cf + (size_t)r0 * N + cc) =
                    make_float2(acc[i][j][0], acc[i][j][1]);
                *(float2*)(Cf + (size_t)(r0 + 8) * N + cc) =
                    make_float2(acc[i][j][2], acc[i][j][3]);
            }
        }
}

// ---------------- V transpose: g_qkvh V section -> [b,h,d,s] ---------------
__global__ void transpose_v() {
    __shared__ __half t[32][33];
    const int bh = blockIdx.z;
    const int s0 = blockIdx.x * 32;
    const int d0 = blockIdx.y * 32;
    const int b = bh / NHEADS, h = bh % NHEADS;
    const int tx = threadIdx.x & 31, ty = threadIdx.x >> 5;
#pragma unroll
    for (int k = 0; k < 4; k++) {
        int s = s0 + ty + k * 8;
        t[ty + k * 8][tx] =
            g_qkvh[((size_t)b * SLEN + s) * NQKV + 2 * DMODEL + h * HDIM + d0 + tx];
    }
    __syncthreads();
#pragma unroll
    for (int k = 0; k < 4; k++) {
        int d = d0 + ty + k * 8;
        g_vT[((size_t)bh * HDIM + d) * SLEN + s0 + tx] = t[tx][ty + k * 8];
    }
}

// ---------------- fp16 flash attention, BQ=128, ldmatrix -------------------
#define QSTR 72
__global__ __launch_bounds__(256)
void attn_mma() {
    __shared__ __half Qs[128][QSTR];
    __shared__ __half Ks[64][QSTR];
    __shared__ __half Vs[64][QSTR];   // [d][key]

    const int tid  = threadIdx.x;
    const int lane = tid & 31;
    const int w    = tid >> 5;
    const int gid  = lane >> 2;
    const int tig  = lane & 3;
    const int qt = blockIdx.x, h = blockIdx.y, b = blockIdx.z;
    const int qbase = qt * 128;
    const size_t rowb = (size_t)b * SLEN;
    const int bh = b * NHEADS + h;
    const __half2 qscale = __floats2half2_rn(0.125f, 0.125f);

    const uint32_t qB = s2u(&Qs[0][0]);
    const uint32_t kB = s2u(&Ks[0][0]);
    const uint32_t vB = s2u(&Vs[0][0]);

    // Load Q tile (128x64), scaled by 1/8
#pragma unroll
    for (int t = 0; t < 8; t++) {
        int c = tid + t * 256;
        int r = c >> 4, dc = (c & 15) << 2;
        uint2 v = *(const uint2*)(g_qkvh + (rowb + qbase + r) * NQKV + h * HDIM + dc);
        *(__half2*)&Qs[r][dc]     = __hmul2(*reinterpret_cast<__half2*>(&v.x), qscale);
        *(__half2*)&Qs[r][dc + 2] = __hmul2(*reinterpret_cast<__half2*>(&v.y), qscale);
    }

    float m[2] = {-1e30f, -1e30f}, l[2] = {0.f, 0.f};
    float o[8][4];
#pragma unroll
    for (int j = 0; j < 8; j++)
#pragma unroll
        for (int e = 0; e < 4; e++) o[j][e] = 0.f;

    const int arow  = lane & 15;
    const int acolB = ((lane >> 4) << 3) * 2;
    const int brow  = ((lane >> 4) << 3) + (lane & 7);
    const int bcolB = (((lane >> 3) & 1) << 3) * 2;
    const int row0 = qbase + w * 16 + gid;
    const int row1 = row0 + 8;

    const int nkt = 2 * qt + 2;
    for (int kt = 0; kt < nkt; kt++) {
        const int kb = kt * 64;
        __syncthreads();
#pragma unroll
        for (int t = 0; t < 4; t++) {
            int c = tid + t * 256;
            int r = c >> 4, dc = (c & 15) << 2;
            *(uint2*)&Ks[r][dc] = *(const uint2*)(
                g_qkvh + (rowb + kb + r) * NQKV + DMODEL + h * HDIM + dc);
            *(uint2*)&Vs[r][dc] = *(const uint2*)(
                g_vT + ((size_t)bh * HDIM + r) * SLEN + kb + dc);
        }
        __syncthreads();

        // S = (Q/8) @ K^T
        float s[8][4];
#pragma unroll
        for (int j = 0; j < 8; j++)
#pragma unroll
            for (int e = 0; e < 4; e++) s[j][e] = 0.f;
#pragma unroll
        for (int kk = 0; kk < 64; kk += 16) {
            uint32_t aq[4];
            ldsm4(aq, qB + (uint32_t)((w * 16 + arow) * (QSTR * 2) + kk * 2 + acolB));
#pragma unroll
            for (int jp = 0; jp < 4; jp++) {
                uint32_t bk[4];
                ldsm4(bk, kB + (uint32_t)((jp * 16 + brow) * (QSTR * 2) + kk * 2 + bcolB));
                mma_f16(s[2 * jp],     aq, &bk[0]);
                mma_f16(s[2 * jp + 1], aq, &bk[2]);
            }
        }

        // causal mask
        if (kb + 63 > row0) {
#pragma unroll
            for (int j = 0; j < 8; j++) {
                int c0 = kb + 8 * j + 2 * tig;
                if (c0 > row0)     s[j][0] = -1e30f;
                if (c0 + 1 > row0) s[j][1] = -1e30f;
                if (c0 > row1)     s[j][2] = -1e30f;
                if (c0 + 1 > row1) s[j][3] = -1e30f;
            }
        }

        // online softmax
        float mt0 = -1e30f, mt1 = -1e30f;
#pragma unroll
        for (int j = 0; j < 8; j++) {
            mt0 = fmaxf(mt0, fmaxf(s[j][0], s[j][1]));
            mt1 = fmaxf(mt1, fmaxf(s[j][2], s[j][3]));
        }
#pragma unroll
        for (int off = 1; off <= 2; off <<= 1) {
            mt0 = fmaxf(mt0, __shfl_xor_sync(0xffffffffu, mt0, off));
            mt1 = fmaxf(mt1, __shfl_xor_sync(0xffffffffu, mt1, off));
        }
        float mn0 = fmaxf(m[0], mt0), mn1 = fmaxf(m[1], mt1);
        float corr0 = __expf(m[0] - mn0), corr1 = __expf(m[1] - mn1);
        m[0] = mn0; m[1] = mn1;
        float rs0 = 0.f, rs1 = 0.f;
#pragma unroll
        for (int j = 0; j < 8; j++) {
            s[j][0] = __expf(s[j][0] - mn0);
            s[j][1] = __expf(s[j][1] - mn0);
            s[j][2] = __expf(s[j][2] - mn1);
            s[j][3] = __expf(s[j][3] - mn1);
            rs0 += s[j][0] + s[j][1];
            rs1 += s[j][2] + s[j][3];
        }
#pragma unroll
        for (int off = 1; off <= 2; off <<= 1) {
            rs0 += __shfl_xor_sync(0xffffffffu, rs0, off);
            rs1 += __shfl_xor_sync(0xffffffffu, rs1, off);
        }
        l[0] = l[0] * corr0 + rs0;
        l[1] = l[1] * corr1 + rs1;
#pragma unroll
        for (int j = 0; j < 8; j++) {
            o[j][0] *= corr0; o[j][1] *= corr0;
            o[j][2] *= corr1; o[j][3] *= corr1;
        }

        // P fragments (C-layout == A-layout), then O += P @ V
        uint32_t pa[4][4];
#pragma unroll
        for (int kc = 0; kc < 4; kc++) {
            pa[kc][0] = pack2(s[2 * kc][0], s[2 * kc][1]);
            pa[kc][1] = pack2(s[2 * kc][2], s[2 * kc][3]);
            pa[kc][2] = pack2(s[2 * kc + 1][0], s[2 * kc + 1][1]);
            pa[kc][3] = pack2(s[2 * kc + 1][2], s[2 * kc + 1][3]);
        }
#pragma unroll
        for (int kc = 0; kc < 4; kc++)
#pragma unroll
            for (int jp = 0; jp < 4; jp++) {
                uint32_t bv[4];
                ldsm4(bv, vB + (uint32_t)((jp * 16 + brow) * (QSTR * 2) +
                                          kc * 32 + bcolB));
                mma_f16(o[2 * jp],     pa[kc], &bv[0]);
                mma_f16(o[2 * jp + 1], pa[kc], &bv[2]);
            }
    }

    // normalize, store fp16 ctx
    const float inv0 = 1.f / l[0], inv1 = 1.f / l[1];
    const size_t r0g = rowb + qbase + w * 16 + gid;
#pragma unroll
    for (int j = 0; j < 8; j++) {
        int col = h * HDIM + 8 * j + 2 * tig;
        *(__half2*)(g_ctxh + r0g * DMODEL + col) =
            __floats2half2_rn(o[j][0] * inv0, o[j][1] * inv0);
        *(__half2*)(g_ctxh + (r0g + 8) * DMODEL + col) =
            __floats2half2_rn(o[j][2] * inv1, o[j][3] * inv1);
    }
}

// ---------------------------------------------------------------------------
extern "C" void kernel_launch(void* const* d_in, const int* in_sizes, int n_in,
                              void* d_out, int out_size) {
    const float* x     = (const float*)d_in[0];
    const float* w_qkv = (const float*)d_in[1];
    const float* w_out = (const float*)d_in[2];
    float* out = (float*)d_out;

    __half *xh, *wqh, *wql, *woh, *wol, *qkvh, *ctxh;
    cudaGetSymbolAddress((void**)&xh,   g_xh);
    cudaGetSymbolAddress((void**)&wqh,  g_wqkvh);
    cudaGetSymbolAddress((void**)&wql,  g_wqkvl);
    cudaGetSymbolAddress((void**)&woh,  g_wouth);
    cudaGetSymbolAddress((void**)&wol,  g_woutl);
    cudaGetSymbolAddress((void**)&qkvh, g_qkvh);
    cudaGetSymbolAddress((void**)&ctxh, g_ctxh);

    const int smemGemm = 3 * TILEH * 2 * 2;  // 98304 B
    cudaFuncSetAttribute(hgemm2x<true>,
                         cudaFuncAttributeMaxDynamicSharedMemorySize, smemGemm);
    cudaFuncSetAttribute(hgemm2x<false>,
                         cudaFuncAttributeMaxDynamicSharedMemorySize, smemGemm);

    to_half<<<256, 256>>>(x, xh, MROWS * DMODEL / 4);
    split_wT<<<dim3(NQKV / 32, DMODEL / 32), 256>>>(w_qkv, wqh, wql, DMODEL, NQKV);
    split_wT<<<dim3(DMODEL / 32, DMODEL / 32), 256>>>(w_out, woh, wol, DMODEL, DMODEL);

    // QKV projection (fp16 out): [8192,768] @ [768,2304]
    hgemm2x<true><<<dim3(NQKV / 128, MROWS / 128), 256, smemGemm>>>(
        xh, wqh, wql, nullptr, qkvh, MROWS, NQKV, DMODEL);

    transpose_v<<<dim3(SLEN / 32, HDIM / 32, BATCH * NHEADS), 256>>>();

    attn_mma<<<dim3(SLEN / 128, NHEADS, BATCH), 256>>>();

    // output projection (fp32 out): [8192,768] @ [768,768]
    hgemm2x<false><<<dim3(DMODEL / 128, MROWS / 128), 256, smemGemm>>>(
        ctxh, woh, wol, out, nullptr, MROWS, DMODEL, DMODEL);
}

// round 6
// speedup vs baseline: 14.1820x; 1.2712x over previous
#include <cuda_runtime.h>
#include <cuda_fp16.h>
#include <cstdint>
#include <cstddef>

#define SLEN   4096
#define BATCH  2
#define DMODEL 768
#define NHEADS 12
#define HDIM   64
#define MROWS  (BATCH * SLEN)   // 8192
#define NQKV   (3 * DMODEL)     // 2304

// ---------------- scratch (__device__ globals) -----------------------------
__device__ __half g_xh[(size_t)MROWS * DMODEL];
__device__ __half g_wqkvh[(size_t)DMODEL * NQKV];   // [N][K]
__device__ __half g_wouth[(size_t)DMODEL * DMODEL]; // [N][K]
__device__ __half g_qkvh[(size_t)MROWS * NQKV];     // fp16 Q|K|V
__device__ __half g_vT[(size_t)BATCH * NHEADS * HDIM * SLEN]; // V^T [b,h,d,s]
__device__ __half g_ctxh[(size_t)MROWS * DMODEL];

// ---------------- helpers --------------------------------------------------
__device__ __forceinline__ uint32_t s2u(const void* p) {
    return (uint32_t)__cvta_generic_to_shared(p);
}
__device__ __forceinline__ uint32_t swz(uint32_t b) {           // SW128
    return b ^ ((b >> 3) & 0x70);
}
__device__ __forceinline__ void ldsm4(uint32_t r[4], uint32_t addr) {
    asm volatile("ldmatrix.sync.aligned.m8n8.x4.shared.b16 {%0,%1,%2,%3}, [%4];"
                 : "=r"(r[0]), "=r"(r[1]), "=r"(r[2]), "=r"(r[3]) : "r"(addr));
}
__device__ __forceinline__ void cp16(uint32_t dst, const void* src) {
    asm volatile("cp.async.cg.shared.global [%0], [%1], 16;" :: "r"(dst), "l"(src));
}
__device__ __forceinline__ void mma_f16(float c[4], const uint32_t a[4],
                                        const uint32_t b[2]) {
    asm volatile(
        "mma.sync.aligned.m16n8k16.row.col.f32.f16.f16.f32 "
        "{%0,%1,%2,%3}, {%4,%5,%6,%7}, {%8,%9}, {%0,%1,%2,%3};\n"
        : "+f"(c[0]), "+f"(c[1]), "+f"(c[2]), "+f"(c[3])
        : "r"(a[0]), "r"(a[1]), "r"(a[2]), "r"(a[3]), "r"(b[0]), "r"(b[1]));
}
__device__ __forceinline__ unsigned pack2(float x, float y) {
    __half2 h = __floats2half2_rn(x, y);
    return *reinterpret_cast<unsigned*>(&h);
}

// ---------------- converts -------------------------------------------------
__global__ void to_half(const float* __restrict__ src, __half* __restrict__ dst, int n4) {
    int i = blockIdx.x * blockDim.x + threadIdx.x;
    int stride = gridDim.x * blockDim.x;
    for (; i < n4; i += stride) {
        float4 v = reinterpret_cast<const float4*>(src)[i];
        reinterpret_cast<__half2*>(dst)[2 * i]     = __floats2half2_rn(v.x, v.y);
        reinterpret_cast<__half2*>(dst)[2 * i + 1] = __floats2half2_rn(v.z, v.w);
    }
}

// W[K][N] fp32 -> WT[N][K] fp16 (transpose + convert)
__global__ void conv_wT(const float* __restrict__ W, __half* __restrict__ WT,
                        int K, int N) {
    __shared__ float t[32][33];
    const int k0 = blockIdx.y * 32, n0 = blockIdx.x * 32;
    const int tx = threadIdx.x & 31, ty = threadIdx.x >> 5;
#pragma unroll
    for (int m = 0; m < 4; m++)
        t[ty + 8 * m][tx] = W[(size_t)(k0 + ty + 8 * m) * N + n0 + tx];
    __syncthreads();
#pragma unroll
    for (int m = 0; m < 4; m++)
        WT[(size_t)(n0 + ty + 8 * m) * K + k0 + tx] = __float2half_rn(t[tx][ty + 8 * m]);
}

// ---------------- 1-pass fp16 GEMM: C = A @ B^T ----------------------------
// A[M][K] fp16, Bt[N][K] fp16 (K-major). 128x128 tile, BK=64, 256 thr,
// cp.async double buffer + SW128 + ldmatrix. 64KB dyn smem -> 2 CTAs/SM.
#define GBUF 32768   // bytes per buffer (A 16K + B 16K)
template <bool WRITE_HALF>
__global__ __launch_bounds__(256, 2)
void hgemm(const __half* __restrict__ A, const __half* __restrict__ Bt,
           float* __restrict__ Cf, __half* __restrict__ Ch,
           int M, int N, int K) {
    extern __shared__ __half sm[];
    const int tid = threadIdx.x, lane = tid & 31, w = tid >> 5;
    const int gid = lane >> 2, tig = lane & 3;
    const int wm = (w >> 2) * 64, wn = (w & 3) * 32;
    const int bm = blockIdx.y * 128, bn = blockIdx.x * 128;
    const uint32_t sb = s2u(sm);

    float acc[4][4][4];
#pragma unroll
    for (int i = 0; i < 4; i++)
#pragma unroll
        for (int j = 0; j < 4; j++)
#pragma unroll
            for (int e = 0; e < 4; e++) acc[i][j][e] = 0.f;

    const int nit = K >> 6;

#define G_LOAD(k0, buf)                                                         \
    {                                                                           \
        uint32_t bb = sb + (uint32_t)(buf) * GBUF;                              \
        _Pragma("unroll")                                                       \
        for (int p = 0; p < 4; p++) {                                           \
            int id = tid + p * 256;                                             \
            int row = id >> 3, chB = (id & 7) << 4;                             \
            uint32_t so = swz((uint32_t)(row * 128 + chB));                     \
            cp16(bb + so,                                                       \
                 (const char*)(A + (size_t)(bm + row) * K + (k0)) + chB);       \
            cp16(bb + 16384 + so,                                               \
                 (const char*)(Bt + (size_t)(bn + row) * K + (k0)) + chB);      \
        }                                                                       \
        asm volatile("cp.async.commit_group;" ::: "memory");                    \
    }

    G_LOAD(0, 0);

    const int arow  = lane & 15;
    const int acolB = ((lane >> 4) << 3) * 2;
    const int brow  = ((lane >> 4) << 3) + (lane & 7);
    const int bcolB = (((lane >> 3) & 1) << 3) * 2;

    for (int it = 0; it < nit; it++) {
        asm volatile("cp.async.wait_group 0;" ::: "memory");
        __syncthreads();
        if (it + 1 < nit) G_LOAD((it + 1) << 6, (it + 1) & 1);

        uint32_t aB = sb + (uint32_t)(it & 1) * GBUF;
        uint32_t bB = aB + 16384;
#pragma unroll
        for (int kk = 0; kk < 64; kk += 16) {
            uint32_t af[4][4];
#pragma unroll
            for (int i = 0; i < 4; i++)
                ldsm4(af[i], aB + swz((uint32_t)((wm + 16 * i + arow) * 128 +
                                                 kk * 2 + acolB)));
#pragma unroll
            for (int jp = 0; jp < 2; jp++) {
                uint32_t bh[4];
                ldsm4(bh, bB + swz((uint32_t)((wn + 16 * jp + brow) * 128 +
                                              kk * 2 + bcolB)));
#pragma unroll
                for (int i = 0; i < 4; i++) {
                    mma_f16(acc[i][2 * jp],     af[i], &bh[0]);
                    mma_f16(acc[i][2 * jp + 1], af[i], &bh[2]);
                }
            }
        }
        __syncthreads();
    }

    // epilogue
#pragma unroll
    for (int i = 0; i < 4; i++)
#pragma unroll
        for (int j = 0; j < 4; j++) {
            int r0 = bm + wm + i * 16 + gid;
            int cc = bn + wn + j * 8 + 2 * tig;
            if (WRITE_HALF) {
                *(__half2*)(Ch + (size_t)r0 * N + cc) =
                    __floats2half2_rn(acc[i][j][0], acc[i][j][1]);
                *(__half2*)(Ch + (size_t)(r0 + 8) * N + cc) =
                    __floats2half2_rn(acc[i][j][2], acc[i][j][3]);
            } else {
                *(float2*)(Cf + (size_t)r0 * N + cc) =
                    make_float2(acc[i][j][0], acc[i][j][1]);
                *(float2*)(Cf + (size_t)(r0 + 8) * N + cc) =
                    make_float2(acc[i][j][2], acc[i][j][3]);
            }
        }
}

// ---------------- V transpose: g_qkvh V section -> [b,h,d,s] ---------------
__global__ void transpose_v() {
    __shared__ __half t[32][33];
    const int bh = blockIdx.z;
    const int s0 = blockIdx.x * 32;
    const int d0 = blockIdx.y * 32;
    const int b = bh / NHEADS, h = bh % NHEADS;
    const int tx = threadIdx.x & 31, ty = threadIdx.x >> 5;
#pragma unroll
    for (int k = 0; k < 4; k++) {
        int s = s0 + ty + k * 8;
        t[ty + k * 8][tx] =
            g_qkvh[((size_t)b * SLEN + s) * NQKV + 2 * DMODEL + h * HDIM + d0 + tx];
    }
    __syncthreads();
#pragma unroll
    for (int k = 0; k < 4; k++) {
        int d = d0 + ty + k * 8;
        g_vT[((size_t)bh * HDIM + d) * SLEN + s0 + tx] = t[tx][ty + k * 8];
    }
}

// ---------------- fp16 flash attention, BQ=128, cp.async double buffer -----
// dyn smem halves: Q[128][72] @0; K[2][64][72] @9216; V[2][64][72] @18432
#define QSTR 72
#define ATT_KOFF 9216
#define ATT_VOFF 18432
#define ATT_BUFH 4608
#define ATT_SMEM (27648 * 2)
__global__ __launch_bounds__(256)
void attn_mma() {
    extern __shared__ __half asm_[];
    const uint32_t sb = s2u(asm_);
    const int tid  = threadIdx.x;
    const int lane = tid & 31;
    const int w    = tid >> 5;
    const int gid  = lane >> 2;
    const int tig  = lane & 3;
    const int qt = blockIdx.x, h = blockIdx.y, b = blockIdx.z;
    const int qbase = qt * 128;
    const size_t rowb = (size_t)b * SLEN;
    const int bh = b * NHEADS + h;
    const __half2 qscale = __floats2half2_rn(0.125f, 0.125f);

    // Load Q tile (128x64), scaled by 1/8 (exact power of 2)
#pragma unroll
    for (int t = 0; t < 8; t++) {
        int c = tid + t * 256;
        int r = c >> 4, dc = (c & 15) << 2;
        uint2 v = *(const uint2*)(g_qkvh + (rowb + qbase + r) * NQKV + h * HDIM + dc);
        *(__half2*)&asm_[r * QSTR + dc]     = __hmul2(*reinterpret_cast<__half2*>(&v.x), qscale);
        *(__half2*)&asm_[r * QSTR + dc + 2] = __hmul2(*reinterpret_cast<__half2*>(&v.y), qscale);
    }

#define KV_LOAD(kb_, buf_)                                                         \
    {                                                                              \
        _Pragma("unroll")                                                          \
        for (int p = 0; p < 2; p++) {                                              \
            int id = tid + p * 256;                                                \
            int r = id >> 3, chB = (id & 7) << 4;                                  \
            uint32_t off = (uint32_t)(buf_) * (ATT_BUFH * 2) +                     \
                           (uint32_t)(r * (QSTR * 2) + chB);                       \
            cp16(sb + ATT_KOFF * 2 + off,                                          \
                 (const char*)(g_qkvh + (rowb + (kb_) + r) * NQKV + DMODEL +       \
                               h * HDIM) + chB);                                   \
            cp16(sb + ATT_VOFF * 2 + off,                                          \
                 (const char*)(g_vT + ((size_t)bh * HDIM + r) * SLEN + (kb_)) +    \
                 chB);                                                             \
        }                                                                          \
        asm volatile("cp.async.commit_group;" ::: "memory");                       \
    }

    float m[2] = {-1e30f, -1e30f}, l[2] = {0.f, 0.f};
    float o[8][4];
#pragma unroll
    for (int j = 0; j < 8; j++)
#pragma unroll
        for (int e = 0; e < 4; e++) o[j][e] = 0.f;

    const int arow  = lane & 15;
    const int acolB = ((lane >> 4) << 3) * 2;
    const int brow  = ((lane >> 4) << 3) + (lane & 7);
    const int bcolB = (((lane >> 3) & 1) << 3) * 2;
    const int row0 = qbase + w * 16 + gid;
    const int row1 = row0 + 8;
    const uint32_t qB = sb;

    const int nkt = 2 * qt + 2;
    KV_LOAD(0, 0);

    for (int kt = 0; kt < nkt; kt++) {
        const int buf = kt & 1;
        const int kb = kt * 64;
        asm volatile("cp.async.wait_group 0;" ::: "memory");
        __syncthreads();
        if (kt + 1 < nkt) KV_LOAD(kb + 64, buf ^ 1);

        const uint32_t kB = sb + ATT_KOFF * 2 + (uint32_t)buf * (ATT_BUFH * 2);
        const uint32_t vB = sb + ATT_VOFF * 2 + (uint32_t)buf * (ATT_BUFH * 2);

        // S = (Q/8) @ K^T
        float s[8][4];
#pragma unroll
        for (int j = 0; j < 8; j++)
#pragma unroll
            for (int e = 0; e < 4; e++) s[j][e] = 0.f;
#pragma unroll
        for (int kk = 0; kk < 64; kk += 16) {
            uint32_t aq[4];
            ldsm4(aq, qB + (uint32_t)((w * 16 + arow) * (QSTR * 2) + kk * 2 + acolB));
#pragma unroll
            for (int jp = 0; jp < 4; jp++) {
                uint32_t bk[4];
                ldsm4(bk, kB + (uint32_t)((jp * 16 + brow) * (QSTR * 2) + kk * 2 + bcolB));
                mma_f16(s[2 * jp],     aq, &bk[0]);
                mma_f16(s[2 * jp + 1], aq, &bk[2]);
            }
        }

        // causal mask (only tiles crossing the diagonal)
        if (kb + 63 > row0) {
#pragma unroll
            for (int j = 0; j < 8; j++) {
                int c0 = kb + 8 * j + 2 * tig;
                if (c0 > row0)     s[j][0] = -1e30f;
                if (c0 + 1 > row0) s[j][1] = -1e30f;
                if (c0 > row1)     s[j][2] = -1e30f;
                if (c0 + 1 > row1) s[j][3] = -1e30f;
            }
        }

        // online softmax
        float mt0 = -1e30f, mt1 = -1e30f;
#pragma unroll
        for (int j = 0; j < 8; j++) {
            mt0 = fmaxf(mt0, fmaxf(s[j][0], s[j][1]));
            mt1 = fmaxf(mt1, fmaxf(s[j][2], s[j][3]));
        }
#pragma unroll
        for (int off = 1; off <= 2; off <<= 1) {
            mt0 = fmaxf(mt0, __shfl_xor_sync(0xffffffffu, mt0, off));
            mt1 = fmaxf(mt1, __shfl_xor_sync(0xffffffffu, mt1, off));
        }
        float mn0 = fmaxf(m[0], mt0), mn1 = fmaxf(m[1], mt1);
        float corr0 = __expf(m[0] - mn0), corr1 = __expf(m[1] - mn1);
        m[0] = mn0; m[1] = mn1;
        float rs0 = 0.f, rs1 = 0.f;
#pragma unroll
        for (int j = 0; j < 8; j++) {
            s[j][0] = __expf(s[j][0] - mn0);
            s[j][1] = __expf(s[j][1] - mn0);
            s[j][2] = __expf(s[j][2] - mn1);
            s[j][3] = __expf(s[j][3] - mn1);
            rs0 += s[j][0] + s[j][1];
            rs1 += s[j][2] + s[j][3];
        }
#pragma unroll
        for (int off = 1; off <= 2; off <<= 1) {
            rs0 += __shfl_xor_sync(0xffffffffu, rs0, off);
            rs1 += __shfl_xor_sync(0xffffffffu, rs1, off);
        }
        l[0] = l[0] * corr0 + rs0;
        l[1] = l[1] * corr1 + rs1;
#pragma unroll
        for (int j = 0; j < 8; j++) {
            o[j][0] *= corr0; o[j][1] *= corr0;
            o[j][2] *= corr1; o[j][3] *= corr1;
        }

        // P @ V (P fragments via C-layout == A-layout)
        uint32_t pa[4][4];
#pragma unroll
        for (int kc = 0; kc < 4; kc++) {
            pa[kc][0] = pack2(s[2 * kc][0], s[2 * kc][1]);
            pa[kc][1] = pack2(s[2 * kc][2], s[2 * kc][3]);
            pa[kc][2] = pack2(s[2 * kc + 1][0], s[2 * kc + 1][1]);
            pa[kc][3] = pack2(s[2 * kc + 1][2], s[2 * kc + 1][3]);
        }
#pragma unroll
        for (int kc = 0; kc < 4; kc++)
#pragma unroll
            for (int jp = 0; jp < 4; jp++) {
                uint32_t bv[4];
                ldsm4(bv, vB + (uint32_t)((jp * 16 + brow) * (QSTR * 2) +
                                          kc * 32 + bcolB));
                mma_f16(o[2 * jp],     pa[kc], &bv[0]);
                mma_f16(o[2 * jp + 1], pa[kc], &bv[2]);
            }
    }

    // normalize, store fp16 ctx
    const float inv0 = 1.f / l[0], inv1 = 1.f / l[1];
    const size_t r0g = rowb + qbase + w * 16 + gid;
#pragma unroll
    for (int j = 0; j < 8; j++) {
        int col = h * HDIM + 8 * j + 2 * tig;
        *(__half2*)(g_ctxh + r0g * DMODEL + col) =
            __floats2half2_rn(o[j][0] * inv0, o[j][1] * inv0);
        *(__half2*)(g_ctxh + (r0g + 8) * DMODEL + col) =
            __floats2half2_rn(o[j][2] * inv1, o[j][3] * inv1);
    }
}

// ---------------------------------------------------------------------------
extern "C" void kernel_launch(void* const* d_in, const int* in_sizes, int n_in,
                              void* d_out, int out_size) {
    const float* x     = (const float*)d_in[0];
    const float* w_qkv = (const float*)d_in[1];
    const float* w_out = (const float*)d_in[2];
    float* out = (float*)d_out;

    __half *xh, *wqh, *woh, *qkvh, *ctxh;
    cudaGetSymbolAddress((void**)&xh,   g_xh);
    cudaGetSymbolAddress((void**)&wqh,  g_wqkvh);
    cudaGetSymbolAddress((void**)&woh,  g_wouth);
    cudaGetSymbolAddress((void**)&qkvh, g_qkvh);
    cudaGetSymbolAddress((void**)&ctxh, g_ctxh);

    const int smemGemm = 2 * GBUF;  // 65536 B
    cudaFuncSetAttribute(hgemm<true>,
                         cudaFuncAttributeMaxDynamicSharedMemorySize, smemGemm);
    cudaFuncSetAttribute(hgemm<false>,
                         cudaFuncAttributeMaxDynamicSharedMemorySize, smemGemm);
    cudaFuncSetAttribute(attn_mma,
                         cudaFuncAttributeMaxDynamicSharedMemorySize, ATT_SMEM);

    to_half<<<256, 256>>>(x, xh, MROWS * DMODEL / 4);
    conv_wT<<<dim3(NQKV / 32, DMODEL / 32), 256>>>(w_qkv, wqh, DMODEL, NQKV);
    conv_wT<<<dim3(DMODEL / 32, DMODEL / 32), 256>>>(w_out, woh, DMODEL, DMODEL);

    // QKV projection (fp16 out): [8192,768] @ [768,2304]
    hgemm<true><<<dim3(NQKV / 128, MROWS / 128), 256, smemGemm>>>(
        xh, wqh, nullptr, qkvh, MROWS, NQKV, DMODEL);

    transpose_v<<<dim3(SLEN / 32, HDIM / 32, BATCH * NHEADS), 256>>>();

    attn_mma<<<dim3(SLEN / 128, NHEADS, BATCH), 256, ATT_SMEM>>>();

    // output projection (fp32 out): [8192,768] @ [768,768]
    hgemm<false><<<dim3(DMODEL / 128, MROWS / 128), 256, smemGemm>>>(
        ctxh, woh, out, nullptr, MROWS, DMODEL, DMODEL);
}